// round 8
// baseline (speedup 1.0000x reference)
#include <cuda_runtime.h>
#include <cuda_fp16.h>
#include <cstdint>

#define DEV_INLINE __device__ __forceinline__

constexpr int NN = 8192;   // nodes
constexpr int DF = 256;    // feature dim
constexpr float YSCALE = 4096.f;   // exact pow2: keeps Y out of fp16 subnormals
constexpr int NSM = 148;           // persistent CTA count

// ---------------- intermediates (static device globals; no runtime alloc) ----
__device__ float    g_inv_deg[NN];
__device__ __half   g_Ah[(size_t)NN * NN];     // fp16 copy of adjacency (rn)
__device__ __half   g_ysTh[(size_t)DF * NN];   // [d][j] = fp16( YSCALE*inv_j*(xW)[j][d] )
__device__ float    g_part[NSM][2][128 * 128]; // per-CTA raw partial tiles
__device__ unsigned g_cnt[128];                // per-tile completion counters

// ============================================================================
// helpers (baseline sm_103 ISA only: cp.async, ldmatrix, mma.sync)
// ============================================================================
DEV_INLINE uint32_t smem_u32(const void* p) {
    uint32_t a;
    asm("{ .reg .u64 t; cvta.to.shared.u64 t, %1; cvt.u32.u64 %0, t; }" : "=r"(a) : "l"(p));
    return a;
}
DEV_INLINE void cp16(uint32_t saddr, const void* g) {
    asm volatile("cp.async.cg.shared.global [%0], [%1], 16;" :: "r"(saddr), "l"(g));
}
DEV_INLINE void cp_commit() { asm volatile("cp.async.commit_group;"); }
template <int N> DEV_INLINE void cp_wait() { asm volatile("cp.async.wait_group %0;" :: "n"(N)); }

DEV_INLINE void ldsm4(uint32_t* d, uint32_t addr) {
    asm volatile("ldmatrix.sync.aligned.m8n8.x4.shared.b16 {%0,%1,%2,%3}, [%4];"
                 : "=r"(d[0]), "=r"(d[1]), "=r"(d[2]), "=r"(d[3]) : "r"(addr));
}
DEV_INLINE void mma_f16(float* c, const uint32_t* a, const uint32_t* b) {
    asm volatile(
        "mma.sync.aligned.m16n8k16.row.col.f32.f16.f16.f32 "
        "{%0,%1,%2,%3}, {%4,%5,%6,%7}, {%8,%9}, {%0,%1,%2,%3};"
        : "+f"(c[0]), "+f"(c[1]), "+f"(c[2]), "+f"(c[3])
        : "r"(a[0]), "r"(a[1]), "r"(a[2]), "r"(a[3]), "r"(b[0]), "r"(b[1]));
}

// span partition: CTA c owns global iters [start(c), start(c+1))
DEV_INLINE int span_start(int c) { return (c * 4096) / 37; }   // c*16384/148

// ============================================================================
// Kernel 1: inv_deg[i] = 1/rowsum(A[i,:]); also emits fp16 copy of A.
// Block 0 additionally zeroes the tile counters (replay-safe: runs every call).
// ============================================================================
__global__ void __launch_bounds__(256) rowsum_kernel(const float* __restrict__ A) {
    if (blockIdx.x == 0 && threadIdx.x < 128) g_cnt[threadIdx.x] = 0u;

    int row = blockIdx.x;
    const float4* r4 = reinterpret_cast<const float4*>(A + (size_t)row * NN);
    __half* ah = g_Ah + (size_t)row * NN;
    float s = 0.f;
#pragma unroll
    for (int it = 0; it < (NN / 4) / 256; it++) {
        int idx = it * 256 + threadIdx.x;
        float4 v = r4[idx];
        s += (v.x + v.y) + (v.z + v.w);
        union { __half2 h[2]; uint2 u; } p;
        p.h[0] = __floats2half2_rn(v.x, v.y);
        p.h[1] = __floats2half2_rn(v.z, v.w);
        *reinterpret_cast<uint2*>(ah + (size_t)idx * 4) = p.u;
    }
    __shared__ float red[256];
    red[threadIdx.x] = s;
    __syncthreads();
#pragma unroll
    for (int o = 128; o > 0; o >>= 1) {
        if (threadIdx.x < o) red[threadIdx.x] += red[threadIdx.x + o];
        __syncthreads();
    }
    if (threadIdx.x == 0) g_inv_deg[row] = 1.0f / red[0];
}

// ============================================================================
// Kernel 2: ysTh[d][j] = fp16( YSCALE * inv_deg[j] * (x @ W)[j][d] )
// ============================================================================
__global__ void __launch_bounds__(256) xw_kernel(const float* __restrict__ x,
                                                 const float* __restrict__ W) {
    __shared__ float xs[32][DF + 1];
    int r0 = blockIdx.x * 32;
    for (int idx = threadIdx.x; idx < 32 * DF; idx += 256) {
        int r = idx >> 8, c = idx & 255;
        xs[r][c] = x[(size_t)(r0 + r) * DF + c];
    }
    __syncthreads();

    int tx = threadIdx.x & 63;
    int ty = threadIdx.x >> 6;
    float acc[8][4];
#pragma unroll
    for (int r = 0; r < 8; r++)
#pragma unroll
        for (int c = 0; c < 4; c++) acc[r][c] = 0.f;

    const float4* W4 = reinterpret_cast<const float4*>(W);
#pragma unroll 4
    for (int k = 0; k < DF; k++) {
        float4 w = W4[k * 64 + tx];
        float xv[8];
#pragma unroll
        for (int r = 0; r < 8; r++) xv[r] = xs[ty * 8 + r][k];
#pragma unroll
        for (int r = 0; r < 8; r++) {
            acc[r][0] = fmaf(xv[r], w.x, acc[r][0]);
            acc[r][1] = fmaf(xv[r], w.y, acc[r][1]);
            acc[r][2] = fmaf(xv[r], w.z, acc[r][2]);
            acc[r][3] = fmaf(xv[r], w.w, acc[r][3]);
        }
    }
    __syncthreads();
#pragma unroll
    for (int r = 0; r < 8; r++)
#pragma unroll
        for (int c = 0; c < 4; c++) xs[ty * 8 + r][tx * 4 + c] = acc[r][c];
    __syncthreads();

    int d = threadIdx.x;
#pragma unroll
    for (int r = 0; r < 32; r += 4) {
        float s0 = g_inv_deg[r0 + r + 0] * YSCALE;
        float s1 = g_inv_deg[r0 + r + 1] * YSCALE;
        float s2 = g_inv_deg[r0 + r + 2] * YSCALE;
        float s3 = g_inv_deg[r0 + r + 3] * YSCALE;
        union { __half2 h[2]; uint2 u; } p;
        p.h[0] = __floats2half2_rn(xs[r + 0][d] * s0, xs[r + 1][d] * s1);
        p.h[1] = __floats2half2_rn(xs[r + 2][d] * s2, xs[r + 3][d] * s3);
        *reinterpret_cast<uint2*>(&g_ysTh[(size_t)d * NN + r0 + r]) = p.u;
    }
}

// ============================================================================
// Kernel 3: persistent span GEMM with FUSED split-K reduction + epilogue.
// 148 CTAs, ~111 global k-iters each. BM=128, BN=128, BK=64, fp16 mma.sync,
// 3-stage cp.async, 512 threads. On each partial-tile flush, the last
// contributing CTA (ticket counter) reduces the <=3 segments in fixed order
// and writes out = relu(inv_deg_i/YSCALE * sum + bias).
// ============================================================================
constexpr int BK = 64;
constexpr int ROWH = (BK + 8) * 2;            // 144 B per 64-half row (padded)
constexpr int TILE_B = 128 * ROWH;            // 18432
constexpr int STAGE_B = 2 * TILE_B;           // 36864 (A + B)
constexpr int STAGES = 3;
constexpr int SMEM_GEMM = STAGES * STAGE_B;   // 110592

__global__ void __launch_bounds__(512, 1) gcn_gemm_kernel(const float* __restrict__ bias,
                                                          float* __restrict__ out) {
    extern __shared__ char smem[];
    __shared__ int s_last;
    const uint32_t sbase = smem_u32(smem);

    const int tid  = threadIdx.x;
    const int wid  = tid >> 5;
    const int lane = tid & 31;
    const int wm   = wid >> 2;          // 0..3 : 32-row slab
    const int wn   = wid & 3;           // 0..3 : 32-col slab
    const int cta  = blockIdx.x;

    const int start = span_start(cta);
    const int end   = span_start(cta + 1);

    const int g2 = lane >> 2, t2 = lane & 3;
    const int q = lane >> 3, r = lane & 7;
    const uint32_t aoff = (uint32_t)((wm * 32 + (q & 1) * 8 + r) * ROWH + (q >> 1) * 16);
    const uint32_t boff = (uint32_t)((wn * 32 + (q >> 1) * 8 + r) * ROWH + (q & 1) * 16);

    // --- stage loader for global iter gi: A 1024 + B 1024 16B chunks
    auto load_stage = [&](int st, int gi) {
        const int tile = gi >> 7, kit = gi & 127;
        const int mb = (tile >> 1) * 128, nb = (tile & 1) * 128, k0 = kit * BK;
        const uint32_t sA = sbase + st * STAGE_B;
        const uint32_t sB = sA + TILE_B;
#pragma unroll
        for (int i = 0; i < 4; i++) {
            int c = i * 512 + tid;            // 0..2047
            if (c < 1024) {
                int row = c >> 3, cq = c & 7;
                cp16(sA + row * ROWH + cq * 16,
                     g_Ah + (size_t)(mb + row) * NN + k0 + cq * 8);
            } else {
                int c2 = c - 1024;
                int row = c2 >> 3, cq = c2 & 7;
                cp16(sB + row * ROWH + cq * 16,
                     g_ysTh + (size_t)(nb + row) * NN + k0 + cq * 8);
            }
        }
    };

    float acc[2][4][4];
#pragma unroll
    for (int mt = 0; mt < 2; mt++)
#pragma unroll
        for (int nt = 0; nt < 4; nt++)
#pragma unroll
            for (int i = 0; i < 4; i++) acc[mt][nt][i] = 0.f;

    // --- prologue (span length >= 110, so start+1 < end always)
    load_stage(0, start); cp_commit();
    load_stage(1, start + 1); cp_commit();

    int st = 0, seg = 0;
    for (int gi = start; gi < end; gi++) {
        cp_wait<1>();
        __syncthreads();

        int pst = st + 2 >= STAGES ? st + 2 - STAGES : st + 2;
        if (gi + 2 < end) load_stage(pst, gi + 2);
        cp_commit();

        const uint32_t sA = sbase + st * STAGE_B;
        const uint32_t sB = sA + TILE_B;
#pragma unroll
        for (int ks = 0; ks < 4; ks++) {       // 4 x k16 steps
            uint32_t afr[2][4];
#pragma unroll
            for (int mt = 0; mt < 2; mt++)
                ldsm4(afr[mt], sA + aoff + mt * (16 * ROWH) + ks * 32);
            uint32_t bfr[2][4];
#pragma unroll
            for (int np = 0; np < 2; np++)
                ldsm4(bfr[np], sB + boff + np * (16 * ROWH) + ks * 32);
#pragma unroll
            for (int mt = 0; mt < 2; mt++)
#pragma unroll
                for (int nt = 0; nt < 4; nt++)
                    mma_f16(acc[mt][nt], afr[mt], &bfr[nt >> 1][(nt & 1) * 2]);
        }

        // --- flush partial tile at tile boundary / span end (uniform branch)
        if ((gi & 127) == 127 || gi == end - 1) {
            const int tile = gi >> 7;
            float* p = &g_part[cta][seg][0];
#pragma unroll
            for (int mt = 0; mt < 2; mt++) {
                const int rl = wm * 32 + mt * 16 + g2;
#pragma unroll
                for (int nt = 0; nt < 4; nt++) {
                    const int col = wn * 32 + nt * 8 + t2 * 2;
                    *reinterpret_cast<float2*>(p + rl * 128 + col) =
                        make_float2(acc[mt][nt][0], acc[mt][nt][1]);
                    *reinterpret_cast<float2*>(p + (rl + 8) * 128 + col) =
                        make_float2(acc[mt][nt][2], acc[mt][nt][3]);
#pragma unroll
                    for (int i = 0; i < 4; i++) acc[mt][nt][i] = 0.f;
                }
            }
            seg = 1;

            // --- ticket: last contributor reduces + writes output
            __syncthreads();                 // all partial stores issued
            if (tid == 0) {
                const int lo = tile << 7, hi = lo + 127;
                int ns = 0;
                int cc = (lo * NSM) >> 14; if (cc > 0) cc--;
                for (; cc < NSM; cc++) {
                    if (span_start(cc) > hi) break;
                    if (span_start(cc + 1) > lo) ns++;
                }
                __threadfence();             // release partial stores
                s_last = (atomicAdd(&g_cnt[tile], 1u) + 1u == (unsigned)ns);
            }
            __syncthreads();
            if (s_last) {
                __threadfence();             // acquire other CTAs' partials
                const int lo = tile << 7, hi = lo + 127;
                const float* segp[4];
                int ns = 0;
                int cc = (lo * NSM) >> 14; if (cc > 0) cc--;
                for (; cc < NSM && ns < 4; cc++) {
                    const int cs = span_start(cc);
                    if (cs > hi) break;
                    if (span_start(cc + 1) > lo)
                        segp[ns++] = &g_part[cc][(tile == (cs >> 7)) ? 0 : 1][0];
                }
                const int mb = (tile >> 1) * 128, nb = (tile & 1) * 128;
#pragma unroll
                for (int v = 0; v < 8; v++) {
                    const int e = (v * 512 + tid) * 4;
                    const int row = e >> 7, col = e & 127;
                    float4 s = make_float4(0.f, 0.f, 0.f, 0.f);
                    for (int g = 0; g < ns; g++) {
                        const float4 pv = *reinterpret_cast<const float4*>(segp[g] + e);
                        s.x += pv.x; s.y += pv.y; s.z += pv.z; s.w += pv.w;
                    }
                    const float sinv = g_inv_deg[mb + row] * (1.0f / YSCALE);
                    const float4 b = *reinterpret_cast<const float4*>(bias + nb + col);
                    float4 o;
                    o.x = fmaxf(fmaf(s.x, sinv, b.x), 0.f);
                    o.y = fmaxf(fmaf(s.y, sinv, b.y), 0.f);
                    o.z = fmaxf(fmaf(s.z, sinv, b.z), 0.f);
                    o.w = fmaxf(fmaf(s.w, sinv, b.w), 0.f);
                    *reinterpret_cast<float4*>(out + (size_t)(mb + row) * DF + nb + col) = o;
                }
            }
        }
        st = st + 1 >= STAGES ? 0 : st + 1;
    }
}

// ============================================================================
// Launch
// ============================================================================
extern "C" void kernel_launch(void* const* d_in, const int* in_sizes, int n_in,
                              void* d_out, int out_size) {
    const float* x    = (const float*)d_in[0];   // [8192,256]
    const float* adj  = (const float*)d_in[1];   // [8192,8192]
    const float* W    = (const float*)d_in[2];   // [256,256]
    const float* bias = (const float*)d_in[3];   // [256]
    float* out = (float*)d_out;                  // [8192,256]

    cudaFuncSetAttribute(gcn_gemm_kernel, cudaFuncAttributeMaxDynamicSharedMemorySize,
                         SMEM_GEMM);

    rowsum_kernel<<<NN, 256>>>(adj);
    xw_kernel<<<NN / 32, 256>>>(x, W);
    gcn_gemm_kernel<<<NSM, 512, SMEM_GEMM>>>(bias, out);
}